// round 3
// baseline (speedup 1.0000x reference)
#include <cuda_runtime.h>

#define BATCH  4
#define CCH    64
#define NPIX   16384
#define NHEADS 8
#define DHEAD  64
#define INNER  512
#define EPSN   1e-12f

typedef unsigned long long ull;

__device__ __forceinline__ ull splat2(float a) {
    unsigned u = __float_as_uint(a);
    ull r; asm("mov.b64 %0, {%1, %1};" : "=l"(r) : "r"(u)); return r;
}
__device__ __forceinline__ void fma2(ull& d, ull a, ull b) {
    asm("fma.rn.f32x2 %0, %1, %2, %0;" : "+l"(d) : "l"(a), "l"(b));
}
__device__ __forceinline__ float2 unpk(ull v) {
    unsigned lo, hi; asm("mov.b64 {%0, %1}, %2;" : "=r"(lo), "=r"(hi) : "l"(v));
    return make_float2(__uint_as_float(lo), __uint_as_float(hi));
}

// ---------------- scratch ------------------------------------------------------
__device__ float    g_G[BATCH * CCH * CCH];   // zero-init at load; re-zeroed by attn
__device__ float    g_P[BATCH * CCH * CCH];   // zero-init at load; re-zeroed by out
__device__ unsigned g_cntG[BATCH];
__device__ unsigned g_cntP[BATCH];

// ---------------- K1: Gram (upper triangle, n-major smem, f32x2) --------------
#define NCHUNK 128
#define TS     68                             // xsT row stride (floats), mult of 4
#define GRAM_THREADS 160
#define GRAM_SMEM (NCHUNK * TS * 4)

__global__ void __launch_bounds__(GRAM_THREADS)
gram_kernel(const float* __restrict__ x) {
    extern __shared__ float xsT[];            // [128][68]  (n-major)
    const int b     = blockIdx.x >> 7;
    const int chunk = blockIdx.x & 127;
    const int n0    = chunk * NCHUNK;
    const int tid   = threadIdx.x;

    const float* xb = x + (size_t)b * CCH * NPIX + n0;
    for (int i = tid; i < CCH * (NCHUNK / 4); i += GRAM_THREADS) {
        int row = i >> 5, q = i & 31;
        float4 v = *(const float4*)(xb + (size_t)row * NPIX + q * 4);
        xsT[(q * 4 + 0) * TS + row] = v.x;
        xsT[(q * 4 + 1) * TS + row] = v.y;
        xsT[(q * 4 + 2) * TS + row] = v.z;
        xsT[(q * 4 + 3) * TS + row] = v.w;
    }
    __syncthreads();

    if (tid < 136) {
        int i = 0, base = 0;
        while (base + (16 - i) <= tid) { base += 16 - i; i++; }
        int j = i + (tid - base);

        ull acc[4][2];
        #pragma unroll
        for (int u = 0; u < 4; u++) { acc[u][0] = 0ull; acc[u][1] = 0ull; }

        const int ia = i * 4, ja = j * 4;
        #pragma unroll 4
        for (int n = 0; n < NCHUNK; n++) {
            float4 a4 = *(const float4*)&xsT[n * TS + ia];
            ulonglong2 bv = *(const ulonglong2*)&xsT[n * TS + ja];
            ull s0 = splat2(a4.x), s1 = splat2(a4.y), s2 = splat2(a4.z), s3 = splat2(a4.w);
            fma2(acc[0][0], s0, bv.x); fma2(acc[0][1], s0, bv.y);
            fma2(acc[1][0], s1, bv.x); fma2(acc[1][1], s1, bv.y);
            fma2(acc[2][0], s2, bv.x); fma2(acc[2][1], s2, bv.y);
            fma2(acc[3][0], s3, bv.x); fma2(acc[3][1], s3, bv.y);
        }

        float* Gb = g_G + b * CCH * CCH;
        #pragma unroll
        for (int u = 0; u < 4; u++) {
            float2 p0 = unpk(acc[u][0]), p1 = unpk(acc[u][1]);
            float g0 = p0.x, g1 = p0.y, g2 = p1.x, g3 = p1.y;
            atomicAdd(&Gb[(ia + u) * CCH + ja + 0], g0);
            atomicAdd(&Gb[(ia + u) * CCH + ja + 1], g1);
            atomicAdd(&Gb[(ia + u) * CCH + ja + 2], g2);
            atomicAdd(&Gb[(ia + u) * CCH + ja + 3], g3);
            if (i != j) {
                atomicAdd(&Gb[(ja + 0) * CCH + ia + u], g0);
                atomicAdd(&Gb[(ja + 1) * CCH + ia + u], g1);
                atomicAdd(&Gb[(ja + 2) * CCH + ia + u], g2);
                atomicAdd(&Gb[(ja + 3) * CCH + ia + u], g3);
            }
        }
    }
}

// ---------------- K2: attention in channel space ------------------------------
#define S68 68
#define OFF_G    0
#define OFF_WQ   (OFF_G  + CCH * 65)
#define OFF_WK   (OFF_WQ + CCH * CCH)
#define OFF_T1   (OFF_WK + CCH * CCH)
#define OFF_T2   (OFF_T1 + CCH * S68)
#define OFF_A    (OFF_T2 + CCH * S68)
#define OFF_WP   (OFF_A  + CCH * S68)
#define OFF_WVT  (OFF_WP + CCH * CCH)
#define OFF_QN   (OFF_WVT + CCH * S68)
#define OFF_KN   (OFF_QN + CCH)
#define ATTN_SMEM ((OFF_KN + CCH) * 4)

__global__ void __launch_bounds__(256)
attn_kernel(const float* __restrict__ Wq,
            const float* __restrict__ Wk,
            const float* __restrict__ Wv,
            const float* __restrict__ Wp,
            const float* __restrict__ rescale,
            float* __restrict__ attn_out) {
    extern __shared__ float sm[];
    float* Gs  = sm + OFF_G;
    float* Wqs = sm + OFF_WQ;
    float* Wks = sm + OFF_WK;
    float* T1  = sm + OFF_T1;
    float* T2  = sm + OFF_T2;
    float* As  = sm + OFF_A;
    float* Wps = sm + OFF_WP;
    float* WvT = sm + OFF_WVT;
    float* qn  = sm + OFF_QN;
    float* kn  = sm + OFF_KN;
    __shared__ int s_last;

    const int b   = blockIdx.x >> 3;
    const int h   = blockIdx.x & 7;
    const int tid = threadIdx.x;
    const int ti  = tid >> 4, tj = tid & 15;
    const int r0  = ti * 4,   e0 = tj * 4;

    for (int i = tid; i < CCH * CCH; i += 256) {
        int r = i >> 6, c = i & 63;
        Gs[r * 65 + c] = g_G[b * CCH * CCH + i];
        Wqs[i] = Wq[r * INNER + h * DHEAD + c];
        Wks[i] = Wk[r * INNER + h * DHEAD + c];
    }
    if (tid == 0) {
        // counter incremented only after this block's G reads have completed
        __threadfence_block();
    }
    __syncthreads();
    if (tid == 0) s_last = (atomicAdd(&g_cntG[b], 1u) == NHEADS - 1) ? 1 : 0;

    // T1 = G @ Wq, T2 = G @ Wk (fused, f32x2 paired over e)
    {
        ull aq[4][2], ak[4][2];
        #pragma unroll
        for (int u = 0; u < 4; u++) { aq[u][0]=aq[u][1]=ak[u][0]=ak[u][1]=0ull; }

        for (int c = 0; c < CCH; c++) {
            float a0 = Gs[(r0 + 0) * 65 + c], a1 = Gs[(r0 + 1) * 65 + c];
            float a2 = Gs[(r0 + 2) * 65 + c], a3 = Gs[(r0 + 3) * 65 + c];
            ulonglong2 bq = *(const ulonglong2*)&Wqs[c * CCH + e0];
            ulonglong2 bk = *(const ulonglong2*)&Wks[c * CCH + e0];
            ull s0 = splat2(a0), s1 = splat2(a1), s2 = splat2(a2), s3 = splat2(a3);
            fma2(aq[0][0], s0, bq.x); fma2(aq[0][1], s0, bq.y);
            fma2(aq[1][0], s1, bq.x); fma2(aq[1][1], s1, bq.y);
            fma2(aq[2][0], s2, bq.x); fma2(aq[2][1], s2, bq.y);
            fma2(aq[3][0], s3, bq.x); fma2(aq[3][1], s3, bq.y);
            fma2(ak[0][0], s0, bk.x); fma2(ak[0][1], s0, bk.y);
            fma2(ak[1][0], s1, bk.x); fma2(ak[1][1], s1, bk.y);
            fma2(ak[2][0], s2, bk.x); fma2(ak[2][1], s2, bk.y);
            fma2(ak[3][0], s3, bk.x); fma2(ak[3][1], s3, bk.y);
        }
        #pragma unroll
        for (int u = 0; u < 4; u++) {
            float2 q0 = unpk(aq[u][0]), q1 = unpk(aq[u][1]);
            float2 k0 = unpk(ak[u][0]), k1 = unpk(ak[u][1]);
            *(float4*)&T1[(r0 + u) * S68 + e0] = make_float4(q0.x, q0.y, q1.x, q1.y);
            *(float4*)&T2[(r0 + u) * S68 + e0] = make_float4(k0.x, k0.y, k1.x, k1.y);
        }
    }
    __syncthreads();

    // inverse norms
    if (tid < 128) {
        const int e = tid & 63;
        const float* W = (tid < 64) ? Wqs : Wks;
        const float* T = (tid < 64) ? T1  : T2;
        float s = 0.f;
        #pragma unroll 8
        for (int c = 0; c < CCH; c++) s = fmaf(W[c * CCH + e], T[c * S68 + e], s);
        ((tid < 64) ? qn : kn)[e] = 1.f / fmaxf(sqrtf(s), EPSN);
    }

    // A_raw = T2^T @ Wq
    {
        ull acc[4][2];
        #pragma unroll
        for (int u = 0; u < 4; u++) { acc[u][0] = acc[u][1] = 0ull; }
        for (int c = 0; c < CCH; c++) {
            float4 av = *(const float4*)&T2[c * S68 + r0];
            ulonglong2 bv = *(const ulonglong2*)&Wqs[c * CCH + e0];
            ull s0 = splat2(av.x), s1 = splat2(av.y), s2 = splat2(av.z), s3 = splat2(av.w);
            fma2(acc[0][0], s0, bv.x); fma2(acc[0][1], s0, bv.y);
            fma2(acc[1][0], s1, bv.x); fma2(acc[1][1], s1, bv.y);
            fma2(acc[2][0], s2, bv.x); fma2(acc[2][1], s2, bv.y);
            fma2(acc[3][0], s3, bv.x); fma2(acc[3][1], s3, bv.y);
        }
        #pragma unroll
        for (int u = 0; u < 4; u++) {
            float2 p0 = unpk(acc[u][0]), p1 = unpk(acc[u][1]);
            *(float4*)&As[(r0 + u) * S68 + e0] = make_float4(p0.x, p0.y, p1.x, p1.y);
        }
    }

    // stage Wp_h and Wv_h^T
    for (int i = tid; i < CCH * CCH; i += 256) {
        int r = i >> 6, c = i & 63;
        Wps[i] = Wp[(h * DHEAD + r) * CCH + c];
        WvT[c * S68 + r] = Wv[r * INNER + h * DHEAD + c];
    }
    __syncthreads();

    // scaled softmax (4 lanes per row)
    {
        const int d = tid >> 2, g = tid & 3;
        float* row = As + d * S68;
        const float sk = kn[d] * rescale[h];
        float vals[16];
        float mx = -1e30f;
        #pragma unroll
        for (int k = 0; k < 16; k++) {
            int e = g + 4 * k;
            float v = row[e] * sk * qn[e];
            vals[k] = v;
            mx = fmaxf(mx, v);
        }
        mx = fmaxf(mx, __shfl_xor_sync(0xffffffffu, mx, 1));
        mx = fmaxf(mx, __shfl_xor_sync(0xffffffffu, mx, 2));
        float s = 0.f;
        #pragma unroll
        for (int k = 0; k < 16; k++) { vals[k] = __expf(vals[k] - mx); s += vals[k]; }
        s += __shfl_xor_sync(0xffffffffu, s, 1);
        s += __shfl_xor_sync(0xffffffffu, s, 2);
        float inv = 1.f / s;
        #pragma unroll
        for (int k = 0; k < 16; k++) row[g + 4 * k] = vals[k] * inv;
    }
    __syncthreads();

    float* ao = attn_out + (size_t)(b * NHEADS + h) * DHEAD * DHEAD;
    for (int i = tid; i < CCH * CCH; i += 256)
        ao[i] = As[(i >> 6) * S68 + (i & 63)];

    // M[e][c] = sum_d A[d][e] * Wp[d][c]  -> T1
    {
        ull acc[4][2];
        #pragma unroll
        for (int u = 0; u < 4; u++) { acc[u][0] = acc[u][1] = 0ull; }
        for (int d = 0; d < CCH; d++) {
            float4 av = *(const float4*)&As[d * S68 + r0];
            ulonglong2 bv = *(const ulonglong2*)&Wps[d * CCH + e0];
            ull s0 = splat2(av.x), s1 = splat2(av.y), s2 = splat2(av.z), s3 = splat2(av.w);
            fma2(acc[0][0], s0, bv.x); fma2(acc[0][1], s0, bv.y);
            fma2(acc[1][0], s1, bv.x); fma2(acc[1][1], s1, bv.y);
            fma2(acc[2][0], s2, bv.x); fma2(acc[2][1], s2, bv.y);
            fma2(acc[3][0], s3, bv.x); fma2(acc[3][1], s3, bv.y);
        }
        #pragma unroll
        for (int u = 0; u < 4; u++) {
            float2 p0 = unpk(acc[u][0]), p1 = unpk(acc[u][1]);
            *(float4*)&T1[(r0 + u) * S68 + e0] = make_float4(p0.x, p0.y, p1.x, p1.y);
        }
    }
    __syncthreads();

    // P[cin][c] += Wv[cin][:] @ M[:][c]
    {
        ull acc[4][2];
        #pragma unroll
        for (int u = 0; u < 4; u++) { acc[u][0] = acc[u][1] = 0ull; }
        for (int e = 0; e < CCH; e++) {
            float4 av = *(const float4*)&WvT[e * S68 + r0];
            ulonglong2 bv = *(const ulonglong2*)&T1[e * S68 + e0];
            ull s0 = splat2(av.x), s1 = splat2(av.y), s2 = splat2(av.z), s3 = splat2(av.w);
            fma2(acc[0][0], s0, bv.x); fma2(acc[0][1], s0, bv.y);
            fma2(acc[1][0], s1, bv.x); fma2(acc[1][1], s1, bv.y);
            fma2(acc[2][0], s2, bv.x); fma2(acc[2][1], s2, bv.y);
            fma2(acc[3][0], s3, bv.x); fma2(acc[3][1], s3, bv.y);
        }
        float* Pb = g_P + b * CCH * CCH;
        #pragma unroll
        for (int u = 0; u < 4; u++) {
            float2 p0 = unpk(acc[u][0]), p1 = unpk(acc[u][1]);
            atomicAdd(&Pb[(r0 + u) * CCH + e0 + 0], p0.x);
            atomicAdd(&Pb[(r0 + u) * CCH + e0 + 1], p0.y);
            atomicAdd(&Pb[(r0 + u) * CCH + e0 + 2], p1.x);
            atomicAdd(&Pb[(r0 + u) * CCH + e0 + 3], p1.y);
        }
    }

    // last head-block of this batch re-zeroes g_G for the next graph replay
    __syncthreads();
    if (s_last) {
        for (int i = tid; i < CCH * CCH; i += 256) g_G[b * CCH * CCH + i] = 0.f;
        if (tid == 0) g_cntG[b] = 0u;
    }
}

// ---------------- K3: out = X @ P + bp (f32x2 paired over channels) -----------
#define ONTILE 128
#define X2S    132
#define OUT_SMEM ((CCH * X2S + CCH * CCH + CCH) * 4)

__global__ void __launch_bounds__(256, 4)
out_kernel(const float* __restrict__ x,
           const float* __restrict__ bp,
           float* __restrict__ out) {
    extern __shared__ float sm[];
    float* xs  = sm;
    float* Ps  = xs + CCH * X2S;
    float* bps = Ps + CCH * CCH;
    __shared__ int s_last;

    const int b     = blockIdx.x >> 7;
    const int chunk = blockIdx.x & 127;
    const int n0    = chunk * ONTILE;
    const int tid   = threadIdx.x;

    for (int i = tid; i < CCH * CCH; i += 256) Ps[i] = g_P[b * CCH * CCH + i];
    if (tid < CCH) bps[tid] = bp[tid];

    const float* xb = x + (size_t)b * CCH * NPIX + n0;
    for (int idx = tid; idx < CCH * (ONTILE / 4); idx += 256) {
        int row = idx >> 5, q4 = idx & 31;
        float4 v = *(const float4*)(xb + (size_t)row * NPIX + q4 * 4);
        *(float4*)(xs + row * X2S + q4 * 4) = v;
    }
    __syncthreads();
    if (tid == 0) s_last = (atomicAdd(&g_cntP[b], 1u) == 127u) ? 1 : 0;

    const int tx = tid & 31;
    const int ty = tid >> 5;
    const int c0 = ty * 8;

    ull acc[4][4];   // [channel-pair][pixel]
    #pragma unroll
    for (int u = 0; u < 4; u++)
        #pragma unroll
        for (int v = 0; v < 4; v++) acc[u][v] = 0ull;

    #pragma unroll 4
    for (int j = 0; j < CCH; j++) {
        float4 xv = *(const float4*)(xs + j * X2S + tx * 4);
        ulonglong2 pA = *(const ulonglong2*)&Ps[j * CCH + c0];
        ulonglong2 pB = *(const ulonglong2*)&Ps[j * CCH + c0 + 4];
        ull s0 = splat2(xv.x), s1 = splat2(xv.y), s2 = splat2(xv.z), s3 = splat2(xv.w);
        fma2(acc[0][0], pA.x, s0); fma2(acc[0][1], pA.x, s1); fma2(acc[0][2], pA.x, s2); fma2(acc[0][3], pA.x, s3);
        fma2(acc[1][0], pA.y, s0); fma2(acc[1][1], pA.y, s1); fma2(acc[1][2], pA.y, s2); fma2(acc[1][3], pA.y, s3);
        fma2(acc[2][0], pB.x, s0); fma2(acc[2][1], pB.x, s1); fma2(acc[2][2], pB.x, s2); fma2(acc[2][3], pB.x, s3);
        fma2(acc[3][0], pB.y, s0); fma2(acc[3][1], pB.y, s1); fma2(acc[3][2], pB.y, s2); fma2(acc[3][3], pB.y, s3);
    }

    #pragma unroll
    for (int u = 0; u < 4; u++) {
        float2 f0 = unpk(acc[u][0]), f1 = unpk(acc[u][1]), f2 = unpk(acc[u][2]), f3 = unpk(acc[u][3]);
        float blo = bps[c0 + 2 * u], bhi = bps[c0 + 2 * u + 1];
        float4 lo = make_float4(f0.x + blo, f1.x + blo, f2.x + blo, f3.x + blo);
        float4 hi = make_float4(f0.y + bhi, f1.y + bhi, f2.y + bhi, f3.y + bhi);
        *(float4*)(out + ((size_t)(b * CCH + c0 + 2 * u + 0)) * NPIX + n0 + tx * 4) = lo;
        *(float4*)(out + ((size_t)(b * CCH + c0 + 2 * u + 1)) * NPIX + n0 + tx * 4) = hi;
    }

    // last block of this batch re-zeroes g_P for the next graph replay
    __syncthreads();
    if (s_last) {
        for (int i = tid; i < CCH * CCH; i += 256) g_P[b * CCH * CCH + i] = 0.f;
        if (tid == 0) g_cntP[b] = 0u;
    }
}

// ---------------- launch ------------------------------------------------------
extern "C" void kernel_launch(void* const* d_in, const int* in_sizes, int n_in,
                              void* d_out, int out_size) {
    const float* x       = (const float*)d_in[0];
    const float* Wq      = (const float*)d_in[1];
    const float* Wk      = (const float*)d_in[2];
    const float* Wv      = (const float*)d_in[3];
    const float* Wp      = (const float*)d_in[4];
    const float* bp      = (const float*)d_in[5];
    const float* rescale = (const float*)d_in[6];

    float* out      = (float*)d_out;
    float* attn_out = out + (size_t)out_size - (size_t)BATCH * NHEADS * DHEAD * DHEAD;

    cudaFuncSetAttribute(gram_kernel, cudaFuncAttributeMaxDynamicSharedMemorySize, GRAM_SMEM);
    cudaFuncSetAttribute(attn_kernel, cudaFuncAttributeMaxDynamicSharedMemorySize, ATTN_SMEM);
    cudaFuncSetAttribute(out_kernel,  cudaFuncAttributeMaxDynamicSharedMemorySize, OUT_SMEM);

    gram_kernel<<<BATCH * 128, GRAM_THREADS, GRAM_SMEM>>>(x);
    attn_kernel<<<BATCH * NHEADS, 256, ATTN_SMEM>>>(Wq, Wk, Wv, Wp, rescale, attn_out);
    out_kernel<<<BATCH * (NPIX / ONTILE), 256, OUT_SMEM>>>(x, bp, out);
}